// round 8
// baseline (speedup 1.0000x reference)
#include <cuda_runtime.h>

#define B_   1024
#define T_   1024
#define HH   64
#define NBR  7
#define NTH  512
#define NBLK 147        // 147*7 = 1029 >= 1024

// ---- shared memory layout (float offsets) ----
// sX/sH rows are chunk-padded: row stride 80, chunk c (16 floats) at word c*20.
// OFF_X ≡ 0 mod 32, OFF_H ≡ 16 mod 32  ->  the 8 (region,chunk) quads of a
// warp's gate load cover all 32 banks exactly once -> 1 wavefront per LDS.128.
#define OFF_WHEAD 0         // 50*68 = 3400
#define OFF_WENCT 3400      // 23*64 = 1472 -> 4872
#define OFF_IN    4880      // 7*24  = 168  -> 5048
#define OFF_X     5056      // 7*80  = 560  -> 5616   (5056 % 32 == 0)
#define OFF_H     5616      // 7*80  = 560  -> 6176   (5616 % 32 == 16)
#define OFF_C     6176      // 448 (linear) -> 6624
#define OFF_GATE  6624      // 7*256 = 1792 -> 8416
#define SM_TOT    8416      // 33664 bytes

// chunked index within a 64-float row
#define XIDX(j) (((j) >> 4) * 20 + ((j) & 15))

#define OFFZ ((size_t)B_ * T_ * 18)
#define OFFH ((size_t)B_ * T_ * 50)
#define OFFC (OFFH + (size_t)B_ * HH)

__device__ __forceinline__ float sigm(float x) {
    return 1.0f / (1.0f + __expf(-x));
}

__global__ __launch_bounds__(NTH, 1)
void wm_lstm_kernel(const float* __restrict__ obs, const float* __restrict__ act,
                    const float* __restrict__ h0,  const float* __restrict__ c0,
                    const float* __restrict__ Wenc, const float* __restrict__ benc,
                    const float* __restrict__ Wih,  const float* __restrict__ Whh,
                    const float* __restrict__ bih,  const float* __restrict__ bhh,
                    const float* __restrict__ Wpred, const float* __restrict__ bpred,
                    const float* __restrict__ Wz,    const float* __restrict__ bz,
                    float* __restrict__ out) {
    __shared__ float sm[SM_TOT];

    const int tid   = threadIdx.x;
    const int bBase = blockIdx.x * NBR;

    // ---- stage head/encoder weights into shared ----
    for (int idx = tid; idx < 50 * 64; idx += NTH) {
        int o = idx >> 6, k = idx & 63;
        sm[OFF_WHEAD + o * 68 + k] = (o < 18) ? Wpred[o * 64 + k] : Wz[(o - 18) * 64 + k];
    }
    for (int idx = tid; idx < 23 * 64; idx += NTH) {
        int k = idx >> 6, j = idx & 63;
        sm[OFF_WENCT + idx] = Wenc[j * 23 + k];   // transposed [k][j]
    }
    if (tid < NBR * 64) {
        int nb = tid >> 6, j = tid & 63;
        int b = bBase + nb;
        float hv = 0.f, cv = 0.f;
        if (b < B_) { hv = h0[(size_t)b * HH + j]; cv = c0[(size_t)b * HH + j]; }
        sm[OFF_H + nb * 80 + XIDX(j)] = hv;
        sm[OFF_C + nb * 64 + j] = cv;
    }

    // ---- gate setup: thread = (gate-block gb of 4 gates, k-chunk kc of 16) ----
    const int gb = tid >> 3;            // 0..63
    const int kc = tid & 7;             // 0..7 : 0-3 -> x chunks, 4-7 -> h chunks
    const int chunk = kc & 3;
    float4 wreg[16];                    // [q][k4] : 4 gates x 16 k = 64 floats
    {
        const float* wsrc = (kc < 4 ? Wih : Whh);
#pragma unroll
        for (int q = 0; q < 4; q++)
#pragma unroll
            for (int k4 = 0; k4 < 4; k4++)
                wreg[q * 4 + k4] = *(const float4*)(wsrc + (gb * 4 + q) * 64 + chunk * 16 + k4 * 4);
    }
    float4 bg4;
    {
        const float4 bi = *(const float4*)(bih + gb * 4);
        const float4 bh2 = *(const float4*)(bhh + gb * 4);
        bg4.x = bi.x + bh2.x; bg4.y = bi.y + bh2.y;
        bg4.z = bi.z + bh2.z; bg4.w = bi.w + bh2.w;
    }
    const float* vbase = sm + (kc < 4 ? OFF_X : OFF_H) + chunk * 20;

    // ---- encoder constants ----
    const float be = (tid < NBR * 64) ? benc[tid & 63] : 0.f;

    // ---- input prefetch: 7*23 = 161 scalars per step ----
    const int  pNb = tid / 23;
    const int  pK  = tid - pNb * 23;
    const int  pb  = bBase + pNb;
    const bool pValid = (tid < NBR * 23) && (pb < B_);
    const float* pPtr = nullptr;
    int pStep = 0;
    if (pValid) {
        if (pK < 18) { pPtr = obs + ((size_t)pb * T_) * 18 + pK;       pStep = 18; }
        else         { pPtr = act + ((size_t)pb * T_) * 5 + (pK - 18); pStep = 5;  }
    }
    float rIn = pValid ? pPtr[0] : 0.f;

    // ---- head constants: one thread per (nb, o) output (350 threads) ----
    const bool headAct = (tid < NBR * 50);
    const int  hNb = tid / 50;
    const int  hO  = tid - hNb * 50;
    const int  hB  = bBase + hNb;
    const bool headW = headAct && (hB < B_);
    const float bh = headAct ? ((hO < 18) ? bpred[hO] : bz[hO - 18]) : 0.f;

    __syncthreads();

    for (int t = 0; t < T_; t++) {
        // A: commit prefetched inputs
        if (tid < NBR * 23) sm[OFF_IN + pNb * 24 + pK] = rIn;
        __syncthreads();

        // B: encoder (chunked sX) + prefetch next input
        if (tid < NBR * 64) {
            int nb = tid >> 6, j = tid & 63;
            float a = be;
#pragma unroll
            for (int k = 0; k < 23; k++)
                a = fmaf(sm[OFF_WENCT + k * 64 + j], sm[OFF_IN + nb * 24 + k], a);
            sm[OFF_X + nb * 80 + XIDX(j)] = fmaxf(a, 0.f);
        }
        if (pValid && (t + 1 < T_)) rIn = __ldg(pPtr + (size_t)(t + 1) * pStep);
        __syncthreads();

        // C: gate GEMM — register-blocked 4 gates x 16 k, 8-lane shfl reduce
#pragma unroll
        for (int nb = 0; nb < NBR; nb++) {
            const float* vp = vbase + nb * 80;
            const float4 v0 = *(const float4*)(vp);
            const float4 v1 = *(const float4*)(vp + 4);
            const float4 v2 = *(const float4*)(vp + 8);
            const float4 v3 = *(const float4*)(vp + 12);
            float a0 = 0.f, a1 = 0.f, a2 = 0.f, a3 = 0.f;
#define GATE_DOT(acc, qq) {                                        \
            const float4 w0 = wreg[(qq)*4+0], w1 = wreg[(qq)*4+1]; \
            const float4 w2 = wreg[(qq)*4+2], w3 = wreg[(qq)*4+3]; \
            acc = fmaf(w0.x, v0.x, acc); acc = fmaf(w0.y, v0.y, acc); \
            acc = fmaf(w0.z, v0.z, acc); acc = fmaf(w0.w, v0.w, acc); \
            acc = fmaf(w1.x, v1.x, acc); acc = fmaf(w1.y, v1.y, acc); \
            acc = fmaf(w1.z, v1.z, acc); acc = fmaf(w1.w, v1.w, acc); \
            acc = fmaf(w2.x, v2.x, acc); acc = fmaf(w2.y, v2.y, acc); \
            acc = fmaf(w2.z, v2.z, acc); acc = fmaf(w2.w, v2.w, acc); \
            acc = fmaf(w3.x, v3.x, acc); acc = fmaf(w3.y, v3.y, acc); \
            acc = fmaf(w3.z, v3.z, acc); acc = fmaf(w3.w, v3.w, acc); }
            GATE_DOT(a0, 0) GATE_DOT(a1, 1) GATE_DOT(a2, 2) GATE_DOT(a3, 3)
#undef GATE_DOT
            // reduce across the 8 k-chunk lanes (xor 1,2,4)
            a0 += __shfl_xor_sync(0xffffffffu, a0, 1);
            a1 += __shfl_xor_sync(0xffffffffu, a1, 1);
            a2 += __shfl_xor_sync(0xffffffffu, a2, 1);
            a3 += __shfl_xor_sync(0xffffffffu, a3, 1);
            a0 += __shfl_xor_sync(0xffffffffu, a0, 2);
            a1 += __shfl_xor_sync(0xffffffffu, a1, 2);
            a2 += __shfl_xor_sync(0xffffffffu, a2, 2);
            a3 += __shfl_xor_sync(0xffffffffu, a3, 2);
            a0 += __shfl_xor_sync(0xffffffffu, a0, 4);
            a1 += __shfl_xor_sync(0xffffffffu, a1, 4);
            a2 += __shfl_xor_sync(0xffffffffu, a2, 4);
            a3 += __shfl_xor_sync(0xffffffffu, a3, 4);
            if (kc == 0) {
                float4 r;
                r.x = a0 + bg4.x; r.y = a1 + bg4.y;
                r.z = a2 + bg4.z; r.w = a3 + bg4.w;
                *(float4*)(sm + OFF_GATE + nb * 256 + gb * 4) = r;
            }
        }
        __syncthreads();

        // D: LSTM cell elementwise (chunked sH)
        if (tid < NBR * 64) {
            int nb = tid >> 6, j = tid & 63;
            const float* gr = sm + OFF_GATE + nb * 256;
            float gi = gr[j], gf = gr[64 + j], gg = gr[128 + j], go = gr[192 + j];
            float cc = sm[OFF_C + nb * 64 + j];
            cc = sigm(gf) * cc + sigm(gi) * tanhf(gg);
            float hh = sigm(go) * tanhf(cc);
            sm[OFF_C + nb * 64 + j] = cc;
            sm[OFF_H + nb * 80 + XIDX(j)] = hh;
        }
        __syncthreads();

        // E: output heads — one thread per (nb, o), chunked h reads
        if (headAct) {
            float a = bh;
            const float* wr = sm + OFF_WHEAD + hO * 68;
            const float* hr = sm + OFF_H + hNb * 80;
#pragma unroll
            for (int i = 0; i < 16; i++) {
                const float4 w = *(const float4*)(wr + i * 4);
                const float4 h = *(const float4*)(hr + (i >> 2) * 20 + (i & 3) * 4);
                a = fmaf(w.x, h.x, a);
                a = fmaf(w.y, h.y, a);
                a = fmaf(w.z, h.z, a);
                a = fmaf(w.w, h.w, a);
            }
            if (headW) {
                size_t row = (size_t)hB * T_ + t;
                if (hO < 18) out[row * 18 + hO] = sigm(a);
                else         out[OFFZ + row * 32 + (hO - 18)] = a;
            }
        }
        // loop-top sync (A) orders E's sH reads vs next D write
    }

    __syncthreads();
    if (tid < NBR * 64) {
        int nb = tid >> 6, j = tid & 63;
        int b = bBase + nb;
        if (b < B_) {
            out[OFFH + (size_t)b * HH + j] = sm[OFF_H + nb * 80 + XIDX(j)];
            out[OFFC + (size_t)b * HH + j] = sm[OFF_C + nb * 64 + j];
        }
    }
}

extern "C" void kernel_launch(void* const* d_in, const int* in_sizes, int n_in,
                              void* d_out, int out_size) {
    (void)in_sizes; (void)n_in; (void)out_size;
    wm_lstm_kernel<<<NBLK, NTH>>>(
        (const float*)d_in[0],  (const float*)d_in[1],
        (const float*)d_in[2],  (const float*)d_in[3],
        (const float*)d_in[4],  (const float*)d_in[5],
        (const float*)d_in[6],  (const float*)d_in[7],
        (const float*)d_in[8],  (const float*)d_in[9],
        (const float*)d_in[10], (const float*)d_in[11],
        (const float*)d_in[12], (const float*)d_in[13],
        (float*)d_out);
}